// round 14
// baseline (speedup 1.0000x reference)
#include <cuda_runtime.h>
#include <math.h>

#define B_  16
#define L_  4096
#define D_  512
#define LP1 (L_ + 1)

// blockDim = 64, grid (4097, 2): one row x one D-half per CTA. Finest CTA
// granularity that still fills the SM (32 CTA slots x 64 thr = 2048 threads).
// CTA-size totals so far: 1024->45.8us, 512->41.5, 256->39.9, 128->39.0.

// fp[d] = f32(100^{-(d - d%2)/D}) + f32(pi/2)*(d%2), generated at COMPILE
// TIME via double pow-by-squaring (validated bit-identical across R3-R13).
struct FpTable { float v[D_]; };

constexpr FpTable make_fp() {
    FpTable t{};
    const double b = 0.9821718891880367;   // 100^(-1/256), correctly rounded
    const float  PI2F = 1.57079637050628662109375f;  // float(pi/2)
    for (int d4 = 0; d4 < D_ / 4; d4++) {
        double p = 1.0, bs = b * b;        // p = b^(2*d4)
        int k = d4;
        for (int i = 0; i < 7; i++) {
            if (k & 1) p *= bs;
            bs *= bs;
            k >>= 1;
        }
        float f0 = (float)p;               // freq at d = 4*d4
        float f1 = (float)(p * b);         // freq at d = 4*d4+2
        t.v[4 * d4 + 0] = f0;
        t.v[4 * d4 + 1] = f0 + PI2F;
        t.v[4 * d4 + 2] = f1;
        t.v[4 * d4 + 3] = f1 + PI2F;
    }
    return t;
}

// Baked into the cubin; L1-resident load in-kernel. No setup node needed.
__device__ constexpr FpTable g_fp = make_fp();

// sin of the f32 angle l*fp (angle formed in f32 exactly like the reference),
// with double-precision Cody-Waite reduction so correctness is independent of
// --use_fast_math (naked sinf would become __sinf and blow up at |x| ~ 1e4).
__device__ __forceinline__ float emb_sin(float lf, float fp) {
    float x = __fmul_rn(lf, fp);                 // matches ref's f32 product
    double xd = (double)x;
    double k  = rint(xd * 0.15915494309189533576888376337251);  // 1/(2*pi)
    double r  = fma(-k, 6.283185307179586476925286766559, xd);  // |r| <= pi
    return sinf((float)r);                        // small-arg: cheap & exact
}

// ===== EXACT R13 per-thread body (kernel 31.7us, regs=32): each thread does
// 4 sins + 16 x (LDG.128, FADD x4, STG.128). Only the (row, d) -> CTA map
// changed: D split across blockIdx.y, no sin work duplicated. ===============
__global__ __launch_bounds__(64)
void pe_kernel(const float* __restrict__ tokens,
               const int*   __restrict__ lengths,
               const float* __restrict__ cls,
               float*       __restrict__ out) {
    // 64 threads cover one 256-wide D-half via float4; one row per CTA.
    int row = blockIdx.x;
    if (row > L_) return;

    int d4 = blockIdx.y * 64 + threadIdx.x;  // float4 index within the row
    int dd = d4 * 4;

    float4 fp   = *reinterpret_cast<const float4*>(g_fp.v + dd);
    float4 cls4 = *reinterpret_cast<const float4*>(cls    + dd);

    // Positional embedding for this (row, dd..dd+3) — computed ONCE, reused
    // across all 16 batch elements. Row L has no embedding.
    float4 emb = make_float4(0.f, 0.f, 0.f, 0.f);
    if (row < L_) {
        float lf = (float)row;
        emb.x = emb_sin(lf, fp.x);
        emb.y = emb_sin(lf, fp.y);
        emb.z = emb_sin(lf, fp.z);
        emb.w = emb_sin(lf, fp.w);
    }

    int lens[B_];
#pragma unroll
    for (int b = 0; b < B_; b++) lens[b] = __ldg(lengths + b);

#pragma unroll
    for (int b = 0; b < B_; b++) {
        float4 o;
        if (row < lens[b]) {
            // valid token: tokens + emb
            const float4 t = *reinterpret_cast<const float4*>(
                tokens + ((size_t)b * L_ + row) * D_ + dd);
            o = make_float4(t.x + emb.x, t.y + emb.y, t.z + emb.z, t.w + emb.w);
        } else if (row == lens[b]) {
            // CLS row (x was zeroed here in the reference, so out = cls)
            o = cls4;
        } else {
            o = make_float4(0.f, 0.f, 0.f, 0.f);
        }
        *reinterpret_cast<float4*>(
            out + ((size_t)b * LP1 + row) * D_ + dd) = o;
    }
}

extern "C" void kernel_launch(void* const* d_in, const int* in_sizes, int n_in,
                              void* d_out, int out_size) {
    const float* tokens  = (const float*)d_in[0];  // [B, L, D] f32
    const int*   lengths = (const int*)  d_in[1];  // [B] i32
    const float* cls     = (const float*)d_in[2];  // [D] f32
    float*       out     = (float*)d_out;          // [B, L+1, D] f32

    (void)in_sizes; (void)n_in; (void)out_size;

    dim3 grid(LP1, 2);                    // 4097 x 2 = 8194 CTAs
    pe_kernel<<<grid, 64>>>(tokens, lengths, cls, out);
}

// round 15
// speedup vs baseline: 1.0326x; 1.0326x over previous
#include <cuda_runtime.h>
#include <math.h>

#define B_  16
#define L_  4096
#define D_  512
#define LP1 (L_ + 1)

// FINAL CONFIGURATION (R13, session optimum):
//   blockDim = 128 (one row per CTA), grid 4097.
//   CTA-size sweep: 1024->45.8us, 512->41.5, 256->39.9, 128->39.0, 64->40.5.
//   Kernel 31.7us = ~200MB end-to-end traffic at ~6.3TB/s effective — at the
//   measured LTS/chip bandwidth ceiling. Flat body at 32 regs beat every
//   structural variant (staging, minBlocks, cache hints, batch/D splits,
//   persistence) across 14 rounds.

// fp[d] = f32(100^{-(d - d%2)/D}) + f32(pi/2)*(d%2), generated at COMPILE
// TIME via double pow-by-squaring (validated bit-identical across R3-R14).
struct FpTable { float v[D_]; };

constexpr FpTable make_fp() {
    FpTable t{};
    const double b = 0.9821718891880367;   // 100^(-1/256), correctly rounded
    const float  PI2F = 1.57079637050628662109375f;  // float(pi/2)
    for (int d4 = 0; d4 < D_ / 4; d4++) {
        double p = 1.0, bs = b * b;        // p = b^(2*d4)
        int k = d4;
        for (int i = 0; i < 7; i++) {
            if (k & 1) p *= bs;
            bs *= bs;
            k >>= 1;
        }
        float f0 = (float)p;               // freq at d = 4*d4
        float f1 = (float)(p * b);         // freq at d = 4*d4+2
        t.v[4 * d4 + 0] = f0;
        t.v[4 * d4 + 1] = f0 + PI2F;
        t.v[4 * d4 + 2] = f1;
        t.v[4 * d4 + 3] = f1 + PI2F;
    }
    return t;
}

// Baked into the cubin; L1-resident load in-kernel. No setup node needed.
__device__ constexpr FpTable g_fp = make_fp();

// sin of the f32 angle l*fp (angle formed in f32 exactly like the reference),
// with double-precision Cody-Waite reduction so correctness is independent of
// --use_fast_math (naked sinf would become __sinf and blow up at |x| ~ 1e4).
__device__ __forceinline__ float emb_sin(float lf, float fp) {
    float x = __fmul_rn(lf, fp);                 // matches ref's f32 product
    double xd = (double)x;
    double k  = rint(xd * 0.15915494309189533576888376337251);  // 1/(2*pi)
    double r  = fma(-k, 6.283185307179586476925286766559, xd);  // |r| <= pi
    return sinf((float)r);                        // small-arg: cheap & exact
}

__global__ __launch_bounds__(128)
void pe_kernel(const float* __restrict__ tokens,
               const int*   __restrict__ lengths,
               const float* __restrict__ cls,
               float*       __restrict__ out) {
    // 128 threads cover D=512 via float4; one row per CTA (rows 0..L).
    int row = blockIdx.x;
    if (row > L_) return;

    int d4 = threadIdx.x;                 // float4 index within the row
    int dd = d4 * 4;

    float4 fp   = *reinterpret_cast<const float4*>(g_fp.v + dd);
    float4 cls4 = *reinterpret_cast<const float4*>(cls    + dd);

    // Positional embedding for this (row, dd..dd+3) — computed ONCE, reused
    // across all 16 batch elements. Row L has no embedding.
    float4 emb = make_float4(0.f, 0.f, 0.f, 0.f);
    if (row < L_) {
        float lf = (float)row;
        emb.x = emb_sin(lf, fp.x);
        emb.y = emb_sin(lf, fp.y);
        emb.z = emb_sin(lf, fp.z);
        emb.w = emb_sin(lf, fp.w);
    }

    int lens[B_];
#pragma unroll
    for (int b = 0; b < B_; b++) lens[b] = __ldg(lengths + b);

#pragma unroll
    for (int b = 0; b < B_; b++) {
        float4 o;
        if (row < lens[b]) {
            // valid token: tokens + emb
            const float4 t = *reinterpret_cast<const float4*>(
                tokens + ((size_t)b * L_ + row) * D_ + dd);
            o = make_float4(t.x + emb.x, t.y + emb.y, t.z + emb.z, t.w + emb.w);
        } else if (row == lens[b]) {
            // CLS row (x was zeroed here in the reference, so out = cls)
            o = cls4;
        } else {
            o = make_float4(0.f, 0.f, 0.f, 0.f);
        }
        *reinterpret_cast<float4*>(
            out + ((size_t)b * LP1 + row) * D_ + dd) = o;
    }
}

extern "C" void kernel_launch(void* const* d_in, const int* in_sizes, int n_in,
                              void* d_out, int out_size) {
    const float* tokens  = (const float*)d_in[0];  // [B, L, D] f32
    const int*   lengths = (const int*)  d_in[1];  // [B] i32
    const float* cls     = (const float*)d_in[2];  // [D] f32
    float*       out     = (float*)d_out;          // [B, L+1, D] f32

    (void)in_sizes; (void)n_in; (void)out_size;

    pe_kernel<<<LP1, 128>>>(tokens, lengths, cls, out);  // 4097 blocks
}

// round 16
// speedup vs baseline: 1.0386x; 1.0057x over previous
#include <cuda_runtime.h>
#include <math.h>

#define B_  16
#define L_  4096
#define D_  512
#define LP1 (L_ + 1)

// FINAL CONFIGURATION (R13/R15, session optimum, reproduced 3x):
//   blockDim = 128 (one row per CTA), grid 4097, regs=32, single graph node.
//   CTA-size sweep: 1024->45.8us, 512->41.5, 256->39.9, 128->39.0, 64->40.5.
//   Kernel 31.6us = ~200MB end-to-end traffic at ~6.33TB/s effective — at the
//   measured LTS/chip bandwidth ceiling (~6300 B/cyc, path-independent).
//   Flat body at 32 regs beat every structural variant tried across 15 rounds
//   (load staging, minBlocks, streaming cache hints, batch split, D split,
//   persistent grid, wide CTAs).

// fp[d] = f32(100^{-(d - d%2)/D}) + f32(pi/2)*(d%2), generated at COMPILE
// TIME via double pow-by-squaring (validated bit-identical across R3-R15:
// rel_err 2.141076e-05 constant under every table-generation scheme).
struct FpTable { float v[D_]; };

constexpr FpTable make_fp() {
    FpTable t{};
    const double b = 0.9821718891880367;   // 100^(-1/256), correctly rounded
    const float  PI2F = 1.57079637050628662109375f;  // float(pi/2)
    for (int d4 = 0; d4 < D_ / 4; d4++) {
        double p = 1.0, bs = b * b;        // p = b^(2*d4)
        int k = d4;
        for (int i = 0; i < 7; i++) {
            if (k & 1) p *= bs;
            bs *= bs;
            k >>= 1;
        }
        float f0 = (float)p;               // freq at d = 4*d4
        float f1 = (float)(p * b);         // freq at d = 4*d4+2
        t.v[4 * d4 + 0] = f0;
        t.v[4 * d4 + 1] = f0 + PI2F;
        t.v[4 * d4 + 2] = f1;
        t.v[4 * d4 + 3] = f1 + PI2F;
    }
    return t;
}

// Baked into the cubin; L1-resident load in-kernel. No setup node needed.
__device__ constexpr FpTable g_fp = make_fp();

// sin of the f32 angle l*fp (angle formed in f32 exactly like the reference),
// with double-precision Cody-Waite reduction so correctness is independent of
// --use_fast_math (naked sinf would become __sinf and blow up at |x| ~ 1e4).
__device__ __forceinline__ float emb_sin(float lf, float fp) {
    float x = __fmul_rn(lf, fp);                 // matches ref's f32 product
    double xd = (double)x;
    double k  = rint(xd * 0.15915494309189533576888376337251);  // 1/(2*pi)
    double r  = fma(-k, 6.283185307179586476925286766559, xd);  // |r| <= pi
    return sinf((float)r);                        // small-arg: cheap & exact
}

__global__ __launch_bounds__(128)
void pe_kernel(const float* __restrict__ tokens,
               const int*   __restrict__ lengths,
               const float* __restrict__ cls,
               float*       __restrict__ out) {
    // 128 threads cover D=512 via float4; one row per CTA (rows 0..L).
    int row = blockIdx.x;
    if (row > L_) return;

    int d4 = threadIdx.x;                 // float4 index within the row
    int dd = d4 * 4;

    float4 fp   = *reinterpret_cast<const float4*>(g_fp.v + dd);
    float4 cls4 = *reinterpret_cast<const float4*>(cls    + dd);

    // Positional embedding for this (row, dd..dd+3) — computed ONCE, reused
    // across all 16 batch elements. Row L has no embedding.
    float4 emb = make_float4(0.f, 0.f, 0.f, 0.f);
    if (row < L_) {
        float lf = (float)row;
        emb.x = emb_sin(lf, fp.x);
        emb.y = emb_sin(lf, fp.y);
        emb.z = emb_sin(lf, fp.z);
        emb.w = emb_sin(lf, fp.w);
    }

    int lens[B_];
#pragma unroll
    for (int b = 0; b < B_; b++) lens[b] = __ldg(lengths + b);

#pragma unroll
    for (int b = 0; b < B_; b++) {
        float4 o;
        if (row < lens[b]) {
            // valid token: tokens + emb
            const float4 t = *reinterpret_cast<const float4*>(
                tokens + ((size_t)b * L_ + row) * D_ + dd);
            o = make_float4(t.x + emb.x, t.y + emb.y, t.z + emb.z, t.w + emb.w);
        } else if (row == lens[b]) {
            // CLS row (x was zeroed here in the reference, so out = cls)
            o = cls4;
        } else {
            o = make_float4(0.f, 0.f, 0.f, 0.f);
        }
        *reinterpret_cast<float4*>(
            out + ((size_t)b * LP1 + row) * D_ + dd) = o;
    }
}

extern "C" void kernel_launch(void* const* d_in, const int* in_sizes, int n_in,
                              void* d_out, int out_size) {
    const float* tokens  = (const float*)d_in[0];  // [B, L, D] f32
    const int*   lengths = (const int*)  d_in[1];  // [B] i32
    const float* cls     = (const float*)d_in[2];  // [D] f32
    float*       out     = (float*)d_out;          // [B, L+1, D] f32

    (void)in_sizes; (void)n_in; (void)out_size;

    pe_kernel<<<LP1, 128>>>(tokens, lengths, cls, out);  // 4097 blocks
}

// round 17
// speedup vs baseline: 1.0403x; 1.0016x over previous
#include <cuda_runtime.h>
#include <math.h>

#define B_  16
#define L_  4096
#define D_  512
#define LP1 (L_ + 1)

// FINAL CONFIGURATION (R13/R15/R16, session optimum, reproduced 3x at
// 39.0/39.2/39.0us total, kernel 31.6-31.8us):
//   blockDim = 128 (one row per CTA), grid 4097, regs=32, single graph node.
//   CTA-size sweep: 1024->45.8us, 512->41.5, 256->39.9, 128->39.0, 64->40.5.
//   Kernel = ~200MB irreducible end-to-end traffic at ~6.33TB/s effective —
//   at the measured LTS/chip bandwidth ceiling (~6300 B/cyc, path-indep).
//   Flat body at 32 regs beat every structural variant tried across 16
//   rounds (load staging, minBlocks, streaming cache hints, batch split,
//   D split, persistent grid, wide CTAs, int4 lens loads).

// fp[d] = f32(100^{-(d - d%2)/D}) + f32(pi/2)*(d%2), generated at COMPILE
// TIME via double pow-by-squaring (validated bit-identical across R3-R16:
// rel_err 2.141076e-05 constant under every table-generation scheme).
struct FpTable { float v[D_]; };

constexpr FpTable make_fp() {
    FpTable t{};
    const double b = 0.9821718891880367;   // 100^(-1/256), correctly rounded
    const float  PI2F = 1.57079637050628662109375f;  // float(pi/2)
    for (int d4 = 0; d4 < D_ / 4; d4++) {
        double p = 1.0, bs = b * b;        // p = b^(2*d4)
        int k = d4;
        for (int i = 0; i < 7; i++) {
            if (k & 1) p *= bs;
            bs *= bs;
            k >>= 1;
        }
        float f0 = (float)p;               // freq at d = 4*d4
        float f1 = (float)(p * b);         // freq at d = 4*d4+2
        t.v[4 * d4 + 0] = f0;
        t.v[4 * d4 + 1] = f0 + PI2F;
        t.v[4 * d4 + 2] = f1;
        t.v[4 * d4 + 3] = f1 + PI2F;
    }
    return t;
}

// Baked into the cubin; L1-resident load in-kernel. No setup node needed.
__device__ constexpr FpTable g_fp = make_fp();

// sin of the f32 angle l*fp (angle formed in f32 exactly like the reference),
// with double-precision Cody-Waite reduction so correctness is independent of
// --use_fast_math (naked sinf would become __sinf and blow up at |x| ~ 1e4).
__device__ __forceinline__ float emb_sin(float lf, float fp) {
    float x = __fmul_rn(lf, fp);                 // matches ref's f32 product
    double xd = (double)x;
    double k  = rint(xd * 0.15915494309189533576888376337251);  // 1/(2*pi)
    double r  = fma(-k, 6.283185307179586476925286766559, xd);  // |r| <= pi
    return sinf((float)r);                        // small-arg: cheap & exact
}

__global__ __launch_bounds__(128)
void pe_kernel(const float* __restrict__ tokens,
               const int*   __restrict__ lengths,
               const float* __restrict__ cls,
               float*       __restrict__ out) {
    // 128 threads cover D=512 via float4; one row per CTA (rows 0..L).
    int row = blockIdx.x;
    if (row > L_) return;

    int d4 = threadIdx.x;                 // float4 index within the row
    int dd = d4 * 4;

    float4 fp   = *reinterpret_cast<const float4*>(g_fp.v + dd);
    float4 cls4 = *reinterpret_cast<const float4*>(cls    + dd);

    // Positional embedding for this (row, dd..dd+3) — computed ONCE, reused
    // across all 16 batch elements. Row L has no embedding.
    float4 emb = make_float4(0.f, 0.f, 0.f, 0.f);
    if (row < L_) {
        float lf = (float)row;
        emb.x = emb_sin(lf, fp.x);
        emb.y = emb_sin(lf, fp.y);
        emb.z = emb_sin(lf, fp.z);
        emb.w = emb_sin(lf, fp.w);
    }

    int lens[B_];
#pragma unroll
    for (int b = 0; b < B_; b++) lens[b] = __ldg(lengths + b);

#pragma unroll
    for (int b = 0; b < B_; b++) {
        float4 o;
        if (row < lens[b]) {
            // valid token: tokens + emb
            const float4 t = *reinterpret_cast<const float4*>(
                tokens + ((size_t)b * L_ + row) * D_ + dd);
            o = make_float4(t.x + emb.x, t.y + emb.y, t.z + emb.z, t.w + emb.w);
        } else if (row == lens[b]) {
            // CLS row (x was zeroed here in the reference, so out = cls)
            o = cls4;
        } else {
            o = make_float4(0.f, 0.f, 0.f, 0.f);
        }
        *reinterpret_cast<float4*>(
            out + ((size_t)b * LP1 + row) * D_ + dd) = o;
    }
}

extern "C" void kernel_launch(void* const* d_in, const int* in_sizes, int n_in,
                              void* d_out, int out_size) {
    const float* tokens  = (const float*)d_in[0];  // [B, L, D] f32
    const int*   lengths = (const int*)  d_in[1];  // [B] i32
    const float* cls     = (const float*)d_in[2];  // [D] f32
    float*       out     = (float*)d_out;          // [B, L+1, D] f32

    (void)in_sizes; (void)n_in; (void)out_size;

    pe_kernel<<<LP1, 128>>>(tokens, lengths, cls, out);  // 4097 blocks
}